// round 15
// baseline (speedup 1.0000x reference)
#include <cuda_runtime.h>
#include <cuda_fp16.h>
#include <cstdint>
#include <math.h>

// DataTransformer, persistent W-resident CTAs, mma.sync fp16 (fp32 accum):
//   out[r,e] = sum_t sim_rt * (x_r . W_t[e,:] + b_t[e]) + x[r,e]
// Grid 152 (1 CTA/SM). Each CTA: one N-half (64 cols), W resident in smem
// (128 KB, loaded once), loops M-tiles of 128 rows (stride 76), x double-buffered,
// ONE __syncthreads per tile, zero syncs in the t/k GEMM loop.
// 512 threads, warp grid 4(M) x 4(N), warp tile 32x16.

#define D_DIM   128
#define T_DIM   8
#define MTILE   128
#define NTILE   64
#define THREADS 512
#define NROWS   65536
#define NMT     512        // number of M-tiles
#define NCTA    152
#define MSTRIDE 76         // NCTA/2 CTAs per N-half

// scratch (static __device__ arrays: allowed scratch form)
__device__ __half g_whi[T_DIM * D_DIM * D_DIM];
__device__ float  g_sim[NROWS * T_DIM];

// ---- smem layout (bytes). Tiles: 256 B rows + XOR-of-16B-chunk swizzle ----
#define OFF_X    0u         // 2 x-buffers x 32768 = 65536
#define OFF_W    65536u     // 8 t-tiles x 16384 (64 rows x 128 K fp16) = 131072
#define OFF_B    196608u    // 8*64 f32 = 2048
#define OFF_SIM  198656u    // 2 buffers x 128*9*4 = 9216
#define SMEM_TOTAL 207872

__device__ __forceinline__ uint32_t smem_u32(const void* p) {
    uint32_t a;
    asm("{ .reg .u64 t; cvta.to.shared.u64 t, %1; cvt.u32.u64 %0, t; }" : "=r"(a) : "l"(p));
    return a;
}

#define CP_ASYNC16(dst, src) \
    asm volatile("cp.async.cg.shared.global [%0], [%1], 16;" :: "r"(dst), "l"(src) : "memory")
#define CP_COMMIT() asm volatile("cp.async.commit_group;" ::: "memory")
#define CP_WAIT0()  asm volatile("cp.async.wait_group 0;" ::: "memory")

#define LDM4(r0, r1, r2, r3, addr) \
    asm volatile("ldmatrix.sync.aligned.m8n8.x4.shared.b16 {%0,%1,%2,%3}, [%4];" \
        : "=r"(r0), "=r"(r1), "=r"(r2), "=r"(r3) : "r"(addr))

#define MMA16816(d, a0, a1, a2, a3, b0, b1) \
    asm volatile("mma.sync.aligned.m16n8k16.row.col.f32.f16.f16.f32 " \
        "{%0,%1,%2,%3}, {%4,%5,%6,%7}, {%8,%9}, {%0,%1,%2,%3};" \
        : "+f"((d)[0]), "+f"((d)[1]), "+f"((d)[2]), "+f"((d)[3]) \
        : "r"(a0), "r"(a1), "r"(a2), "r"(a3), "r"(b0), "r"(b1))

// swizzled byte offset of 16B chunk (r, c), c in [0,16), 256 B rows
__device__ __forceinline__ uint32_t swz(int r, int c) {
    return (uint32_t)(r * 256 + ((c ^ (r & 7)) << 4));
}

// ===================== Kernel 1: W fp32 -> fp16 preconvert =====================
__global__ void conv_kernel(const float* __restrict__ W)
{
    const int W4 = T_DIM * D_DIM * D_DIM / 4;   // 32768 float4
    int i = blockIdx.x * blockDim.x + threadIdx.x;
    if (i < W4) {
        float4 v = reinterpret_cast<const float4*>(W)[i];
        uint32_t hw[4];
        float vf[4] = {v.x, v.y, v.z, v.w};
#pragma unroll
        for (int e = 0; e < 4; e++)
            hw[e] = (uint32_t)__half_as_ushort(__float2half_rn(vf[e]));
        reinterpret_cast<uint2*>(g_whi)[i] =
            make_uint2(hw[0] | (hw[1] << 16), hw[2] | (hw[3] << 16));
    }
}

// ===================== Kernel 2: gating softmax, one warp per row =====================
__global__ void gate_kernel(const float* __restrict__ x, const float* __restrict__ p)
{
    const int wid  = threadIdx.x >> 5;
    const int lane = threadIdx.x & 31;
    const int row  = blockIdx.x * 8 + wid;

    const float4 xv = reinterpret_cast<const float4*>(x + (size_t)row * D_DIM)[lane];
    float xn2 = xv.x * xv.x + xv.y * xv.y + xv.z * xv.z + xv.w * xv.w;
    float dots[T_DIM], pn2[T_DIM];
#pragma unroll
    for (int t = 0; t < T_DIM; t++) {
        const float4 pv = reinterpret_cast<const float4*>(p + t * D_DIM)[lane];
        dots[t] = xv.x * pv.x + xv.y * pv.y + xv.z * pv.z + xv.w * pv.w;
        pn2[t]  = pv.x * pv.x + pv.y * pv.y + pv.z * pv.z + pv.w * pv.w;
    }
#pragma unroll
    for (int o = 16; o > 0; o >>= 1) {
        xn2 += __shfl_xor_sync(0xffffffffu, xn2, o);
#pragma unroll
        for (int t = 0; t < T_DIM; t++) {
            dots[t] += __shfl_xor_sync(0xffffffffu, dots[t], o);
            pn2[t]  += __shfl_xor_sync(0xffffffffu, pn2[t], o);
        }
    }
    const float xn = sqrtf(xn2);
    float cosv[T_DIM], m = -1e30f;
#pragma unroll
    for (int t = 0; t < T_DIM; t++) {
        cosv[t] = dots[t] / (xn * sqrtf(pn2[t]));
        m = fmaxf(m, cosv[t]);
    }
    float ev[T_DIM], sum = 0.f;
#pragma unroll
    for (int t = 0; t < T_DIM; t++) { ev[t] = expf(cosv[t] - m); sum += ev[t]; }
    const float inv = 1.f / sum;
    if (lane == 0) {
        float4 s0 = make_float4(ev[0] * inv, ev[1] * inv, ev[2] * inv, ev[3] * inv);
        float4 s1 = make_float4(ev[4] * inv, ev[5] * inv, ev[6] * inv, ev[7] * inv);
        reinterpret_cast<float4*>(g_sim + (size_t)row * T_DIM)[0] = s0;
        reinterpret_cast<float4*>(g_sim + (size_t)row * T_DIM)[1] = s1;
    }
}

// ===================== Kernel 3: persistent GEMM + fold =====================
__device__ __forceinline__ void stage_tile(char* smem, uint32_t xoff, uint32_t soff,
                                           const float* __restrict__ x, int m, int tid)
{
    const int row0 = m * MTILE;
    // x: fp32 gmem -> fp16 swizzled smem (2048 chunks, 4 per thread)
#pragma unroll
    for (int k = 0; k < 4; k++) {
        int ci = tid + k * THREADS;
        int r = ci >> 4, c = ci & 15;
        const float4* src = reinterpret_cast<const float4*>(
            x + (size_t)(row0 + r) * D_DIM + c * 8);
        float4 v0 = src[0], v1 = src[1];
        uint32_t hw[4];
        hw[0] = (uint32_t)__half_as_ushort(__float2half_rn(v0.x))
              | ((uint32_t)__half_as_ushort(__float2half_rn(v0.y)) << 16);
        hw[1] = (uint32_t)__half_as_ushort(__float2half_rn(v0.z))
              | ((uint32_t)__half_as_ushort(__float2half_rn(v0.w)) << 16);
        hw[2] = (uint32_t)__half_as_ushort(__float2half_rn(v1.x))
              | ((uint32_t)__half_as_ushort(__float2half_rn(v1.y)) << 16);
        hw[3] = (uint32_t)__half_as_ushort(__float2half_rn(v1.z))
              | ((uint32_t)__half_as_ushort(__float2half_rn(v1.w)) << 16);
        *reinterpret_cast<uint4*>(smem + xoff + swz(r, c)) =
            make_uint4(hw[0], hw[1], hw[2], hw[3]);
    }
    // sim: 128 rows x 8 f32 -> smem stride 9
    if (tid < 256) {
        int r = tid >> 1, h = tid & 1;
        float4 s4 = *reinterpret_cast<const float4*>(
            g_sim + (size_t)(row0 + r) * T_DIM + h * 4);
        float* dst = reinterpret_cast<float*>(smem + soff) + r * 9 + h * 4;
        dst[0] = s4.x; dst[1] = s4.y; dst[2] = s4.z; dst[3] = s4.w;
    }
}

__global__ void __launch_bounds__(THREADS, 1)
dt_mma_kernel(const float* __restrict__ x,
              const float* __restrict__ b,
              float* __restrict__ out)
{
    extern __shared__ char smem[];
    const uint32_t sb = smem_u32(smem);
    const int tid  = threadIdx.x;
    const int wid  = tid >> 5;
    const int lane = tid & 31;

    const int nhalf = blockIdx.x & 1;
    const int nbase = nhalf * NTILE;
    const int m0    = blockIdx.x >> 1;           // 0..75

    float* s_b = reinterpret_cast<float*>(smem + OFF_B);

    // ---- Prologue: W (this N-half, all 8 t) via cp.async; b; x(m0)+sim(m0) ----
#pragma unroll
    for (int k = 0; k < 16; k++) {
        int ci = tid + k * THREADS;              // 0..8191
        int t = ci >> 10, li = ci & 1023;
        int r = li >> 4, c = li & 15;
        CP_ASYNC16(sb + OFF_W + (uint32_t)t * 16384u + swz(r, c),
                   g_whi + (size_t)t * (D_DIM * D_DIM) + (size_t)(nbase + r) * D_DIM + c * 8);
    }
    CP_COMMIT();
    if (tid < T_DIM * NTILE)
        s_b[tid] = b[(tid >> 6) * D_DIM + nbase + (tid & 63)];
    if (m0 < NMT)
        stage_tile(smem, OFF_X, OFF_SIM, x, m0, tid);
    CP_WAIT0();
    __syncthreads();

    // ---- Warp tiling: 4(M) x 4(N), warp tile 32x16 ----
    const int wm = wid & 3, wn = wid >> 2;
    const int mbw = wm * 32, nbw = wn * 16;

    const uint32_t arowb = (uint32_t)((mbw + (lane & 15)) * 256);
    const int     achnk  = lane >> 4;
    const uint32_t browb = (uint32_t)((nbw + (lane & 7) + ((lane >> 4) << 3)) * 256);
    const int     bchnk  = (lane >> 3) & 1;
    const int     bank   = lane & 7;
    const int rql = lane >> 2;
    const int cpl = (lane & 3) * 2;

    int buf = 0;
    for (int m = m0; m < NMT; m += MSTRIDE) {
        const uint32_t xb = sb + OFF_X + (uint32_t)buf * 32768u;
        const uint32_t sim = OFF_SIM + (uint32_t)buf * 4608u;
        float* s_sim = reinterpret_cast<float*>(smem + sim);

        // stage next tile into the other buffers (LDG latency hides under MMA)
        const int mnext = m + MSTRIDE;
        if (mnext < NMT)
            stage_tile(smem, OFF_X + (uint32_t)(buf ^ 1) * 32768u,
                       OFF_SIM + (uint32_t)(buf ^ 1) * 4608u, x, mnext, tid);

        // A fragments for this tile, cached across all t (16 LDM4 -> 64 regs)
        uint32_t A[8][8];
#pragma unroll
        for (int k = 0; k < 8; k++) {
            const uint32_t aoff = arowb + (uint32_t)((((2 * k + achnk) ^ bank)) << 4);
            LDM4(A[k][0], A[k][1], A[k][2], A[k][3], xb + aoff);
            LDM4(A[k][4], A[k][5], A[k][6], A[k][7], xb + aoff + 16u * 256u);
        }

        float acc[2][2][4];
#pragma unroll
        for (int i = 0; i < 2; i++)
#pragma unroll
            for (int j = 0; j < 2; j++)
#pragma unroll
                for (int e = 0; e < 4; e++) acc[i][j][e] = 0.f;

        // ---- t-loop: NO barriers, W resident ----
#pragma unroll
        for (int t = 0; t < T_DIM; t++) {
            const uint32_t wt = sb + OFF_W + (uint32_t)t * 16384u;
            float y[2][2][4];
#pragma unroll
            for (int i = 0; i < 2; i++)
#pragma unroll
                for (int j = 0; j < 2; j++)
#pragma unroll
                    for (int e = 0; e < 4; e++) y[i][j][e] = 0.f;

#pragma unroll
            for (int k = 0; k < 8; k++) {
                const uint32_t boff = browb + (uint32_t)((((2 * k + bchnk) ^ bank)) << 4);
                uint32_t b0, b1, b2, b3;
                LDM4(b0, b1, b2, b3, wt + boff);
                MMA16816(y[0][0], A[k][0], A[k][1], A[k][2], A[k][3], b0, b1);
                MMA16816(y[0][1], A[k][0], A[k][1], A[k][2], A[k][3], b2, b3);
                MMA16816(y[1][0], A[k][4], A[k][5], A[k][6], A[k][7], b0, b1);
                MMA16816(y[1][1], A[k][4], A[k][5], A[k][6], A[k][7], b2, b3);
            }

            // fold: acc += sim_t * (y + bias)
#pragma unroll
            for (int mt = 0; mt < 2; mt++) {
                const int rloc = mbw + mt * 16 + rql;
                const float s0 = s_sim[rloc * 9 + t];
                const float s1 = s_sim[(rloc + 8) * 9 + t];
#pragma unroll
                for (int nt = 0; nt < 2; nt++) {
                    const int c = nbw + nt * 8 + cpl;
                    const float bb0 = s_b[t * NTILE + c];
                    const float bb1 = s_b[t * NTILE + c + 1];
                    acc[mt][nt][0] = fmaf(s0, y[mt][nt][0] + bb0, acc[mt][nt][0]);
                    acc[mt][nt][1] = fmaf(s0, y[mt][nt][1] + bb1, acc[mt][nt][1]);
                    acc[mt][nt][2] = fmaf(s1, y[mt][nt][2] + bb0, acc[mt][nt][2]);
                    acc[mt][nt][3] = fmaf(s1, y[mt][nt][3] + bb1, acc[mt][nt][3]);
                }
            }
        }

        // ---- Epilogue: residual (exact fp32 x) + store ----
        const int row0 = m * MTILE;
#pragma unroll
        for (int mt = 0; mt < 2; mt++) {
            const int rg0 = row0 + mbw + mt * 16 + rql;
            const int rg1 = rg0 + 8;
#pragma unroll
            for (int nt = 0; nt < 2; nt++) {
                const int c = nbase + nbw + nt * 8 + cpl;
                float2 xv0 = *reinterpret_cast<const float2*>(x + (size_t)rg0 * D_DIM + c);
                float2 o0  = make_float2(acc[mt][nt][0] + xv0.x, acc[mt][nt][1] + xv0.y);
                *reinterpret_cast<float2*>(out + (size_t)rg0 * D_DIM + c) = o0;
                float2 xv1 = *reinterpret_cast<const float2*>(x + (size_t)rg1 * D_DIM + c);
                float2 o1  = make_float2(acc[mt][nt][2] + xv1.x, acc[mt][nt][3] + xv1.y);
                *reinterpret_cast<float2*>(out + (size_t)rg1 * D_DIM + c) = o1;
            }
        }

        __syncthreads();   // next-buffer stage complete; this buffer free
        buf ^= 1;
    }
}

extern "C" void kernel_launch(void* const* d_in, const int* in_sizes, int n_in,
                              void* d_out, int out_size)
{
    (void)n_in; (void)out_size; (void)in_sizes;
    const float* x = (const float*)d_in[0];   // [B,S,D]
    const float* W = (const float*)d_in[1];   // [T,D,D]
    const float* b = (const float*)d_in[2];   // [T,D]
    const float* p = (const float*)d_in[3];   // [T,1,D]
    float* out = (float*)d_out;

    conv_kernel<<<128, 256>>>(W);
    gate_kernel<<<NROWS / 8, 256>>>(x, p);

    cudaFuncSetAttribute(dt_mma_kernel,
                         cudaFuncAttributeMaxDynamicSharedMemorySize, SMEM_TOTAL);
    dt_mma_kernel<<<NCTA, THREADS, SMEM_TOTAL>>>(x, b, out);
}

// round 16
// speedup vs baseline: 1.0234x; 1.0234x over previous
#include <cuda_runtime.h>
#include <cuda_fp16.h>
#include <cstdint>
#include <math.h>

// DataTransformer via mma.sync, pure fp16 single-pass GEMM (fp32 accumulate).
//   out[r,e] = sum_t sim_rt * (x_r . W_t[e,:] + b_t[e]) + x[r,e]
// Gating softmax in a separate coalesced warp-per-row kernel (exact fp32).
// x converted fp32->fp16 in-kernel (overlaps W cp.async). conv handles W only.
// CTA tile: 128 rows x 64 cols, 256 threads, warp grid 4x2 (tile 32x32). 2 CTAs/SM.

#define D_DIM   128
#define T_DIM   8
#define MTILE   128
#define NTILE   64
#define THREADS 256
#define NROWS   65536

// scratch (static __device__ arrays: allowed scratch form)
__device__ __half g_whi[T_DIM * D_DIM * D_DIM];
__device__ float  g_sim[NROWS * T_DIM];

// ---- smem layout (bytes). Tiles use 256 B rows + XOR-of-16B-chunk swizzle ----
#define OFF_X    0u         // 128x128 fp16 = 32768
#define OFF_W    32768u     // 2 buffers x (64x128 fp16 = 16384) = 32768
#define OFF_B    65536u     // 8*64 f32 = 2048
#define OFF_SIM  67584u     // 128*9*4 = 4608 (fp32, stride 9)
#define SMEM_TOTAL 72192

__device__ __forceinline__ uint32_t smem_u32(const void* p) {
    uint32_t a;
    asm("{ .reg .u64 t; cvta.to.shared.u64 t, %1; cvt.u32.u64 %0, t; }" : "=r"(a) : "l"(p));
    return a;
}

#define CP_ASYNC16(dst, src) \
    asm volatile("cp.async.cg.shared.global [%0], [%1], 16;" :: "r"(dst), "l"(src) : "memory")
#define CP_COMMIT() asm volatile("cp.async.commit_group;" ::: "memory")
#define CP_WAIT1()  asm volatile("cp.async.wait_group 1;" ::: "memory")
#define CP_WAIT0()  asm volatile("cp.async.wait_group 0;" ::: "memory")

#define LDM4(r0, r1, r2, r3, addr) \
    asm volatile("ldmatrix.sync.aligned.m8n8.x4.shared.b16 {%0,%1,%2,%3}, [%4];" \
        : "=r"(r0), "=r"(r1), "=r"(r2), "=r"(r3) : "r"(addr))

#define MMA16816(d, a0, a1, a2, a3, b0, b1) \
    asm volatile("mma.sync.aligned.m16n8k16.row.col.f32.f16.f16.f32 " \
        "{%0,%1,%2,%3}, {%4,%5,%6,%7}, {%8,%9}, {%0,%1,%2,%3};" \
        : "+f"((d)[0]), "+f"((d)[1]), "+f"((d)[2]), "+f"((d)[3]) \
        : "r"(a0), "r"(a1), "r"(a2), "r"(a3), "r"(b0), "r"(b1))

// swizzled byte offset of 16B chunk (r, c), c in [0,16), 256 B rows
__device__ __forceinline__ uint32_t swz(int r, int c) {
    return (uint32_t)(r * 256 + ((c ^ (r & 7)) << 4));
}

// ===================== Kernel 1: W fp32 -> fp16 preconvert (tiny) =====================
__global__ void conv_kernel(const float* __restrict__ W)
{
    const int W4 = T_DIM * D_DIM * D_DIM / 4;   // 32768 float4
    int i = blockIdx.x * blockDim.x + threadIdx.x;
    if (i < W4) {
        float4 v = reinterpret_cast<const float4*>(W)[i];
        uint32_t hw[4];
        float vf[4] = {v.x, v.y, v.z, v.w};
#pragma unroll
        for (int e = 0; e < 4; e++)
            hw[e] = (uint32_t)__half_as_ushort(__float2half_rn(vf[e]));
        reinterpret_cast<uint2*>(g_whi)[i] =
            make_uint2(hw[0] | (hw[1] << 16), hw[2] | (hw[3] << 16));
    }
}

// ===================== Kernel 2: gating softmax, one warp per row (coalesced) =====================
__global__ void gate_kernel(const float* __restrict__ x, const float* __restrict__ p)
{
    const int wid  = threadIdx.x >> 5;
    const int lane = threadIdx.x & 31;
    const int row  = blockIdx.x * 8 + wid;

    const float4 xv = reinterpret_cast<const float4*>(x + (size_t)row * D_DIM)[lane];
    float xn2 = xv.x * xv.x + xv.y * xv.y + xv.z * xv.z + xv.w * xv.w;
    float dots[T_DIM], pn2[T_DIM];
#pragma unroll
    for (int t = 0; t < T_DIM; t++) {
        const float4 pv = reinterpret_cast<const float4*>(p + t * D_DIM)[lane];
        dots[t] = xv.x * pv.x + xv.y * pv.y + xv.z * pv.z + xv.w * pv.w;
        pn2[t]  = pv.x * pv.x + pv.y * pv.y + pv.z * pv.z + pv.w * pv.w;
    }
#pragma unroll
    for (int o = 16; o > 0; o >>= 1) {
        xn2 += __shfl_xor_sync(0xffffffffu, xn2, o);
#pragma unroll
        for (int t = 0; t < T_DIM; t++) {
            dots[t] += __shfl_xor_sync(0xffffffffu, dots[t], o);
            pn2[t]  += __shfl_xor_sync(0xffffffffu, pn2[t], o);
        }
    }
    const float xn = sqrtf(xn2);
    float cosv[T_DIM], m = -1e30f;
#pragma unroll
    for (int t = 0; t < T_DIM; t++) {
        cosv[t] = dots[t] / (xn * sqrtf(pn2[t]));
        m = fmaxf(m, cosv[t]);
    }
    float ev[T_DIM], sum = 0.f;
#pragma unroll
    for (int t = 0; t < T_DIM; t++) { ev[t] = expf(cosv[t] - m); sum += ev[t]; }
    const float inv = 1.f / sum;
    if (lane == 0) {
        float4 s0 = make_float4(ev[0] * inv, ev[1] * inv, ev[2] * inv, ev[3] * inv);
        float4 s1 = make_float4(ev[4] * inv, ev[5] * inv, ev[6] * inv, ev[7] * inv);
        reinterpret_cast<float4*>(g_sim + (size_t)row * T_DIM)[0] = s0;
        reinterpret_cast<float4*>(g_sim + (size_t)row * T_DIM)[1] = s1;
    }
}

// ===================== Kernel 3: GEMM + fold =====================
__device__ __forceinline__ void issue_w_tile(uint32_t sb, uint32_t wbuf, int t, int nbase, int tid)
{
    const size_t wb = (size_t)t * (D_DIM * D_DIM) + (size_t)nbase * D_DIM;
#pragma unroll
    for (int k = 0; k < 4; k++) {
        int ci = tid + k * THREADS;          // 16B chunk index, 1024 per tile (64 rows x 16)
        int r = ci >> 4, c = ci & 15;
        CP_ASYNC16(sb + wbuf + swz(r, c), g_whi + wb + r * D_DIM + c * 8);
    }
}

__global__ void __launch_bounds__(THREADS, 2)
dt_mma_kernel(const float* __restrict__ x,
              const float* __restrict__ b,
              float* __restrict__ out)
{
    extern __shared__ char smem[];
    const uint32_t sb = smem_u32(smem);
    const int tid  = threadIdx.x;
    const int wid  = tid >> 5;
    const int lane = tid & 31;
    const int mblk = blockIdx.x >> 1;
    const int nblk = blockIdx.x & 1;
    const int row0 = mblk * MTILE;
    const int nbase = nblk * NTILE;

    float* s_b   = reinterpret_cast<float*>(smem + OFF_B);
    float* s_sim = reinterpret_cast<float*>(smem + OFF_SIM);

    // W(0), W(1) via cp.async first (they fly during convert + sim load)
    issue_w_tile(sb, OFF_W, 0, nbase, tid);
    CP_COMMIT();
    issue_w_tile(sb, OFF_W + 16384u, 1, nbase, tid);
    CP_COMMIT();

    // b (this CTA's 64-col slice) to smem
#pragma unroll
    for (int i = tid; i < T_DIM * NTILE; i += THREADS)
        s_b[i] = b[(i >> 6) * D_DIM + nbase + (i & 63)];

    // sim (precomputed, coalesced) to smem: 128 rows x 2 float4-halves
    {
        int r = tid >> 1, h = tid & 1;
        float4 s4 = *reinterpret_cast<const float4*>(g_sim + (size_t)(row0 + r) * T_DIM + h * 4);
        float* dst = s_sim + r * 9 + h * 4;
        dst[0] = s4.x; dst[1] = s4.y; dst[2] = s4.z; dst[3] = s4.w;
    }

    // x tile: fp32 gmem -> fp16 swizzled smem (2048 16B chunks, 8 per thread)
#pragma unroll
    for (int k = 0; k < 8; k++) {
        int ci = tid + k * THREADS;
        int r = ci >> 4, c = ci & 15;
        const float4* src = reinterpret_cast<const float4*>(
            x + (size_t)(row0 + r) * D_DIM + c * 8);
        float4 v0 = src[0], v1 = src[1];
        uint32_t hw[4];
        hw[0] = (uint32_t)__half_as_ushort(__float2half_rn(v0.x))
              | ((uint32_t)__half_as_ushort(__float2half_rn(v0.y)) << 16);
        hw[1] = (uint32_t)__half_as_ushort(__float2half_rn(v0.z))
              | ((uint32_t)__half_as_ushort(__float2half_rn(v0.w)) << 16);
        hw[2] = (uint32_t)__half_as_ushort(__float2half_rn(v1.x))
              | ((uint32_t)__half_as_ushort(__float2half_rn(v1.y)) << 16);
        hw[3] = (uint32_t)__half_as_ushort(__float2half_rn(v1.z))
              | ((uint32_t)__half_as_ushort(__float2half_rn(v1.w)) << 16);
        *reinterpret_cast<uint4*>(smem + OFF_X + swz(r, c)) =
            make_uint4(hw[0], hw[1], hw[2], hw[3]);
    }

    CP_WAIT1();        // W(0) complete (W(1) may still be in flight)
    __syncthreads();   // x tile (STS) + W0 + sim + b visible to all

    // ---- Warp tiling: 4(M) x 2(N) grid, warp tile 32x32 ----
    const int wm = wid & 3, wn = wid >> 2;
    const int mbw = wm * 32, nbw = wn * 32;

    // ldmatrix per-lane address parts (swizzled)
    const uint32_t arowb = (uint32_t)((mbw + (lane & 15)) * 256);
    const int     achnk  = lane >> 4;            // 0/1
    const uint32_t browb = (uint32_t)((nbw + (lane & 7) + ((lane >> 4) << 3)) * 256);
    const int     bchnk  = (lane >> 3) & 1;
    const int     bank   = lane & 7;             // == row&7 for both A and B lane->row maps
    const int rql = lane >> 2;
    const int cpl = (lane & 3) * 2;

    float acc[2][4][4];
#pragma unroll
    for (int i = 0; i < 2; i++)
#pragma unroll
        for (int j = 0; j < 4; j++)
#pragma unroll
            for (int e = 0; e < 4; e++) acc[i][j][e] = 0.f;

    for (int t = 0; t < T_DIM; t++) {
        const uint32_t wb = OFF_W + (uint32_t)(t & 1) * 16384u;

        float y[2][4][4];
#pragma unroll
        for (int i = 0; i < 2; i++)
#pragma unroll
            for (int j = 0; j < 4; j++)
#pragma unroll
                for (int e = 0; e < 4; e++) y[i][j][e] = 0.f;

#pragma unroll
        for (int k = 0; k < 8; k++) {
            const uint32_t aoff = arowb + (uint32_t)((((2 * k + achnk) ^ bank)) << 4);
            const uint32_t boff = browb + (uint32_t)((((2 * k + bchnk) ^ bank)) << 4);

            uint32_t ah0, ah1, ah2, ah3, ah4, ah5, ah6, ah7;
            LDM4(ah0, ah1, ah2, ah3, sb + OFF_X + aoff);
            LDM4(ah4, ah5, ah6, ah7, sb + OFF_X + aoff + 16u * 256u);
            uint32_t bh0, bh1, bh2, bh3, bh4, bh5, bh6, bh7;
            LDM4(bh0, bh1, bh2, bh3, sb + wb + boff);
            LDM4(bh4, bh5, bh6, bh7, sb + wb + boff + 16u * 256u);

            MMA16816(y[0][0], ah0, ah1, ah2, ah3, bh0, bh1);
            MMA16816(y[0][1], ah0, ah1, ah2, ah3, bh2, bh3);
            MMA16816(y[0][2], ah0, ah1, ah2, ah3, bh4, bh5);
            MMA16816(y[0][3], ah0, ah1, ah2, ah3, bh6, bh7);
            MMA16816(y[1][0], ah4, ah5, ah6, ah7, bh0, bh1);
            MMA16816(y[1][1], ah4, ah5, ah6, ah7, bh2, bh3);
            MMA16816(y[1][2], ah4, ah5, ah6, ah7, bh4, bh5);
            MMA16816(y[1][3], ah4, ah5, ah6, ah7, bh6, bh7);
        }

        // fold: acc += sim_row * (y + bias_col)
#pragma unroll
        for (int mt = 0; mt < 2; mt++) {
            const int rloc = mbw + mt * 16 + rql;
            const float s0 = s_sim[rloc * 9 + t];
            const float s1 = s_sim[(rloc + 8) * 9 + t];
#pragma unroll
            for (int nt = 0; nt < 4; nt++) {
                const int c = nbw + nt * 8 + cpl;          // local col 0..63
                const float bb0 = s_b[t * NTILE + c];
                const float bb1 = s_b[t * NTILE + c + 1];
                acc[mt][nt][0] = fmaf(s0, y[mt][nt][0] + bb0, acc[mt][nt][0]);
                acc[mt][nt][1] = fmaf(s0, y[mt][nt][1] + bb1, acc[mt][nt][1]);
                acc[mt][nt][2] = fmaf(s1, y[mt][nt][2] + bb0, acc[mt][nt][2]);
                acc[mt][nt][3] = fmaf(s1, y[mt][nt][3] + bb1, acc[mt][nt][3]);
            }
        }

        // pipeline: refill the buffer we just finished with W(t+2)
        if (t < T_DIM - 2) {
            __syncthreads();
            issue_w_tile(sb, OFF_W + (uint32_t)(t & 1) * 16384u, t + 2, nbase, tid);
            CP_COMMIT();
        }
        if (t < T_DIM - 1) {
            if (t < T_DIM - 2) { CP_WAIT1(); } else { CP_WAIT0(); }
            __syncthreads();
        }
    }

    // ---- Epilogue: residual (exact fp32 x from gmem) + store ----
#pragma unroll
    for (int mt = 0; mt < 2; mt++) {
        const int rg0 = row0 + mbw + mt * 16 + rql;
        const int rg1 = rg0 + 8;
#pragma unroll
        for (int nt = 0; nt < 4; nt++) {
            const int c = nbase + nbw + nt * 8 + cpl;       // global col
            float2 xv0 = *reinterpret_cast<const float2*>(x + (size_t)rg0 * D_DIM + c);
            float2 o0  = make_float2(acc[mt][nt][0] + xv0.x, acc[mt][nt][1] + xv0.y);
            *reinterpret_cast<float2*>(out + (size_t)rg0 * D_DIM + c) = o0;
            float2 xv1 = *reinterpret_cast<const float2*>(x + (size_t)rg1 * D_DIM + c);
            float2 o1  = make_float2(acc[mt][nt][2] + xv1.x, acc[mt][nt][3] + xv1.y);
            *reinterpret_cast<float2*>(out + (size_t)rg1 * D_DIM + c) = o1;
        }
    }
}

extern "C" void kernel_launch(void* const* d_in, const int* in_sizes, int n_in,
                              void* d_out, int out_size)
{
    (void)n_in; (void)out_size;
    const float* x = (const float*)d_in[0];   // [B,S,D]
    const float* W = (const float*)d_in[1];   // [T,D,D]
    const float* b = (const float*)d_in[2];   // [T,D]
    const float* p = (const float*)d_in[3];   // [T,1,D]
    float* out = (float*)d_out;

    const int nrows = in_sizes[0] / D_DIM;    // 65536
    const int grid  = (nrows / MTILE) * 2;    // 1024

    conv_kernel<<<128, 256>>>(W);
    gate_kernel<<<nrows / 8, 256>>>(x, p);

    cudaFuncSetAttribute(dt_mma_kernel,
                         cudaFuncAttributeMaxDynamicSharedMemorySize, SMEM_TOTAL);
    dt_mma_kernel<<<grid, THREADS, SMEM_TOTAL>>>(x, b, out);
}

// round 17
// speedup vs baseline: 1.3553x; 1.3243x over previous
#include <cuda_runtime.h>
#include <cuda_fp16.h>
#include <cstdint>
#include <math.h>

// DataTransformer via mma.sync, pure fp16 single-pass GEMM (fp32 accumulate).
//   out[r,e] = sum_t softmax_t(cos(x_r,p_t)) * (x_r . W_t[e,:] + b_t[e]) + x[r,e]
// Gating dots computed ON TENSOR CORES (N=8=T) from the fp16 x tile in smem;
// xn^2 reduced for free during the fp32->fp16 convert (half-warp shfl).
// CTA tile: 128 rows x 64 cols, 256 threads, warp grid 4x2 (tile 32x32). 2 CTAs/SM.

#define D_DIM   128
#define T_DIM   8
#define MTILE   128
#define NTILE   64
#define THREADS 256
#define NROWS   65536

// fp16 W scratch (static __device__ array: allowed scratch form)
__device__ __half g_whi[T_DIM * D_DIM * D_DIM];

// ---- smem layout (bytes). Tiles use 256 B rows + XOR-of-16B-chunk swizzle ----
#define OFF_X    0u         // 128x128 fp16 = 32768
#define OFF_W    32768u     // 2 buffers x 16384 = 32768
#define OFF_B    65536u     // 8*64 f32 = 2048
#define OFF_SIM  67584u     // 128*9*4 = 4608 (fp32, stride 9)
#define OFF_XN2  72192u     // 128 f32
#define OFF_PN2  72704u     // 8 f32
#define SMEM_TOTAL 72736

__device__ __forceinline__ uint32_t smem_u32(const void* p) {
    uint32_t a;
    asm("{ .reg .u64 t; cvta.to.shared.u64 t, %1; cvt.u32.u64 %0, t; }" : "=r"(a) : "l"(p));
    return a;
}

#define CP_ASYNC16(dst, src) \
    asm volatile("cp.async.cg.shared.global [%0], [%1], 16;" :: "r"(dst), "l"(src) : "memory")
#define CP_COMMIT() asm volatile("cp.async.commit_group;" ::: "memory")
#define CP_WAIT1()  asm volatile("cp.async.wait_group 1;" ::: "memory")
#define CP_WAIT0()  asm volatile("cp.async.wait_group 0;" ::: "memory")

#define LDM4(r0, r1, r2, r3, addr) \
    asm volatile("ldmatrix.sync.aligned.m8n8.x4.shared.b16 {%0,%1,%2,%3}, [%4];" \
        : "=r"(r0), "=r"(r1), "=r"(r2), "=r"(r3) : "r"(addr))

#define MMA16816(d, a0, a1, a2, a3, b0, b1) \
    asm volatile("mma.sync.aligned.m16n8k16.row.col.f32.f16.f16.f32 " \
        "{%0,%1,%2,%3}, {%4,%5,%6,%7}, {%8,%9}, {%0,%1,%2,%3};" \
        : "+f"((d)[0]), "+f"((d)[1]), "+f"((d)[2]), "+f"((d)[3]) \
        : "r"(a0), "r"(a1), "r"(a2), "r"(a3), "r"(b0), "r"(b1))

// swizzled byte offset of 16B chunk (r, c), c in [0,16), 256 B rows
__device__ __forceinline__ uint32_t swz(int r, int c) {
    return (uint32_t)(r * 256 + ((c ^ (r & 7)) << 4));
}

// ===================== Kernel 1: W fp32 -> fp16 preconvert (tiny) =====================
__global__ void conv_kernel(const float* __restrict__ W)
{
    const int W4 = T_DIM * D_DIM * D_DIM / 4;   // 32768 float4
    int i = blockIdx.x * blockDim.x + threadIdx.x;
    if (i < W4) {
        float4 v = reinterpret_cast<const float4*>(W)[i];
        uint32_t hw[4];
        float vf[4] = {v.x, v.y, v.z, v.w};
#pragma unroll
        for (int e = 0; e < 4; e++)
            hw[e] = (uint32_t)__half_as_ushort(__float2half_rn(vf[e]));
        reinterpret_cast<uint2*>(g_whi)[i] =
            make_uint2(hw[0] | (hw[1] << 16), hw[2] | (hw[3] << 16));
    }
}

// ===================== Kernel 2: GEMM + tensor-core gating + fold =====================
__device__ __forceinline__ void issue_w_tile(uint32_t sb, uint32_t wbuf, int t, int nbase, int tid)
{
    const size_t wb = (size_t)t * (D_DIM * D_DIM) + (size_t)nbase * D_DIM;
#pragma unroll
    for (int k = 0; k < 4; k++) {
        int ci = tid + k * THREADS;          // 1024 chunks (64 rows x 16)
        int r = ci >> 4, c = ci & 15;
        CP_ASYNC16(sb + wbuf + swz(r, c), g_whi + wb + r * D_DIM + c * 8);
    }
}

__global__ void __launch_bounds__(THREADS, 2)
dt_mma_kernel(const float* __restrict__ x,
              const float* __restrict__ b,
              const float* __restrict__ p,
              float* __restrict__ out)
{
    extern __shared__ char smem[];
    const uint32_t sb = smem_u32(smem);
    const int tid  = threadIdx.x;
    const int wid  = tid >> 5;
    const int lane = tid & 31;
    const int mblk = blockIdx.x >> 1;
    const int nblk = blockIdx.x & 1;
    const int row0 = mblk * MTILE;
    const int nbase = nblk * NTILE;

    float* s_b   = reinterpret_cast<float*>(smem + OFF_B);
    float* s_sim = reinterpret_cast<float*>(smem + OFF_SIM);
    float* s_xn2 = reinterpret_cast<float*>(smem + OFF_XN2);
    float* s_pn2 = reinterpret_cast<float*>(smem + OFF_PN2);

    // W(0), W(1) via cp.async first (fly during convert + gating)
    issue_w_tile(sb, OFF_W, 0, nbase, tid);
    CP_COMMIT();
    issue_w_tile(sb, OFF_W + 16384u, 1, nbase, tid);
    CP_COMMIT();

    // b slice to smem
#pragma unroll
    for (int i = tid; i < T_DIM * NTILE; i += THREADS)
        s_b[i] = b[(i >> 6) * D_DIM + nbase + (i & 63)];

    // pn2 (tiny; 8 threads, exact fp32)
    if (tid < T_DIM) {
        float pn2 = 0.f;
        const float4* pr = reinterpret_cast<const float4*>(p + tid * D_DIM);
#pragma unroll 8
        for (int i = 0; i < 32; i++) {
            float4 pv = pr[i];
            pn2 += pv.x * pv.x + pv.y * pv.y + pv.z * pv.z + pv.w * pv.w;
        }
        s_pn2[tid] = pn2;
    }

    // x tile: fp32 gmem -> fp16 swizzled smem; xn2 reduced per half-warp (same row)
#pragma unroll
    for (int k = 0; k < 8; k++) {
        int ci = tid + k * THREADS;
        int r = ci >> 4, c = ci & 15;
        const float4* src = reinterpret_cast<const float4*>(
            x + (size_t)(row0 + r) * D_DIM + c * 8);
        float4 v0 = src[0], v1 = src[1];
        uint32_t hw[4];
        hw[0] = (uint32_t)__half_as_ushort(__float2half_rn(v0.x))
              | ((uint32_t)__half_as_ushort(__float2half_rn(v0.y)) << 16);
        hw[1] = (uint32_t)__half_as_ushort(__float2half_rn(v0.z))
              | ((uint32_t)__half_as_ushort(__float2half_rn(v0.w)) << 16);
        hw[2] = (uint32_t)__half_as_ushort(__float2half_rn(v1.x))
              | ((uint32_t)__half_as_ushort(__float2half_rn(v1.y)) << 16);
        hw[3] = (uint32_t)__half_as_ushort(__float2half_rn(v1.z))
              | ((uint32_t)__half_as_ushort(__float2half_rn(v1.w)) << 16);
        *reinterpret_cast<uint4*>(smem + OFF_X + swz(r, c)) =
            make_uint4(hw[0], hw[1], hw[2], hw[3]);

        // fp32 sum of squares for this chunk; 16 lanes of the half-warp share row r
        float ss = v0.x * v0.x + v0.y * v0.y + v0.z * v0.z + v0.w * v0.w
                 + v1.x * v1.x + v1.y * v1.y + v1.z * v1.z + v1.w * v1.w;
        ss += __shfl_xor_sync(0xffffffffu, ss, 1);
        ss += __shfl_xor_sync(0xffffffffu, ss, 2);
        ss += __shfl_xor_sync(0xffffffffu, ss, 4);
        ss += __shfl_xor_sync(0xffffffffu, ss, 8);
        if ((tid & 15) == 0) s_xn2[r] = ss;
    }

    __syncthreads();   // x tile + xn2 + pn2 visible

    // ---- Warp tiling constants ----
    const int wm = wid & 3, wn = wid >> 2;
    const int mbw = wm * 32, nbw = wn * 32;

    const uint32_t arowb = (uint32_t)((mbw + (lane & 15)) * 256);
    const int     achnk  = lane >> 4;
    const uint32_t browb = (uint32_t)((nbw + (lane & 7) + ((lane >> 4) << 3)) * 256);
    const int     bchnk  = (lane >> 3) & 1;
    const int     bank   = lane & 7;
    const int rql = lane >> 2;
    const int cpl = (lane & 3) * 2;

    // ---- Gating via tensor core: dots = X(fp16, smem) . P^T, N = 8 ----
    if (wid < 4) {                         // wn==0 warps; rows mbw..mbw+31
        const int q = lane & 3;            // t-pair selector in B frag
        const int n = lane >> 2;           // t index held by this thread's B col
        // p fragments for all 8 k-steps (fp32 gmem -> fp16x2)
        uint32_t pb0[8], pb1[8];
#pragma unroll
        for (int k = 0; k < 8; k++) {
            const float* pr = p + n * D_DIM + 16 * k + 2 * q;
            float2 f0 = *reinterpret_cast<const float2*>(pr);
            float2 f1 = *reinterpret_cast<const float2*>(pr + 8);
            __half2 h0 = __floats2half2_rn(f0.x, f0.y);
            __half2 h1 = __floats2half2_rn(f1.x, f1.y);
            pb0[k] = *reinterpret_cast<uint32_t*>(&h0);
            pb1[k] = *reinterpret_cast<uint32_t*>(&h1);
        }
        float c0[4] = {0.f, 0.f, 0.f, 0.f};   // rows mbw+rql, mbw+8+rql
        float c1[4] = {0.f, 0.f, 0.f, 0.f};   // rows mbw+16+rql, mbw+24+rql
#pragma unroll
        for (int k = 0; k < 8; k++) {
            const uint32_t aoff = arowb + (uint32_t)((((2 * k + achnk) ^ bank)) << 4);
            uint32_t a0, a1, a2, a3, a4, a5, a6, a7;
            LDM4(a0, a1, a2, a3, sb + OFF_X + aoff);
            LDM4(a4, a5, a6, a7, sb + OFF_X + aoff + 16u * 256u);
            MMA16816(c0, a0, a1, a2, a3, pb0[k], pb1[k]);
            MMA16816(c1, a4, a5, a6, a7, pb0[k], pb1[k]);
        }
        // gather all 8 t per row across the quad (lanes share rows within a quad)
        float dA[8], dB[8], dC[8], dD[8];
        const int base = lane & ~3;
#pragma unroll
        for (int s = 0; s < 4; s++) {
            const int ts = 2 * s;
            dA[ts]     = __shfl_sync(0xffffffffu, c0[0], base + s);
            dA[ts + 1] = __shfl_sync(0xffffffffu, c0[1], base + s);
            dB[ts]     = __shfl_sync(0xffffffffu, c0[2], base + s);
            dB[ts + 1] = __shfl_sync(0xffffffffu, c0[3], base + s);
            dC[ts]     = __shfl_sync(0xffffffffu, c1[0], base + s);
            dC[ts + 1] = __shfl_sync(0xffffffffu, c1[1], base + s);
            dD[ts]     = __shfl_sync(0xffffffffu, c1[2], base + s);
            dD[ts + 1] = __shfl_sync(0xffffffffu, c1[3], base + s);
        }
        if ((lane & 3) == 0) {
            const int rows[4] = {mbw + rql, mbw + 8 + rql, mbw + 16 + rql, mbw + 24 + rql};
            float* dall[4] = {dA, dB, dC, dD};
#pragma unroll
            for (int rr = 0; rr < 4; rr++) {
                const float xn = sqrtf(s_xn2[rows[rr]]);
                float cosv[8], m = -1e30f;
#pragma unroll
                for (int t = 0; t < T_DIM; t++) {
                    cosv[t] = dall[rr][t] / (xn * sqrtf(s_pn2[t]));
                    m = fmaxf(m, cosv[t]);
                }
                float ev[8], sum = 0.f;
#pragma unroll
                for (int t = 0; t < T_DIM; t++) { ev[t] = expf(cosv[t] - m); sum += ev[t]; }
                const float inv = 1.f / sum;
#pragma unroll
                for (int t = 0; t < T_DIM; t++)
                    s_sim[rows[rr] * 9 + t] = ev[t] * inv;
            }
        }
    }

    CP_WAIT1();        // W(0) complete
    __syncthreads();   // sim + W0 visible to all

    float acc[2][4][4];
#pragma unroll
    for (int i = 0; i < 2; i++)
#pragma unroll
        for (int j = 0; j < 4; j++)
#pragma unroll
            for (int e = 0; e < 4; e++) acc[i][j][e] = 0.f;

    for (int t = 0; t < T_DIM; t++) {
        const uint32_t wb = OFF_W + (uint32_t)(t & 1) * 16384u;

        float y[2][4][4];
#pragma unroll
        for (int i = 0; i < 2; i++)
#pragma unroll
            for (int j = 0; j < 4; j++)
#pragma unroll
                for (int e = 0; e < 4; e++) y[i][j][e] = 0.f;

#pragma unroll
        for (int k = 0; k < 8; k++) {
            const uint32_t aoff = arowb + (uint32_t)((((2 * k + achnk) ^ bank)) << 4);
            const uint32_t boff = browb + (uint32_t)((((2 * k + bchnk) ^ bank)) << 4);

            uint32_t ah0, ah1, ah2, ah3, ah4, ah5, ah6, ah7;
            LDM4(ah0, ah1, ah2, ah3, sb + OFF_X + aoff);
            LDM4(ah4, ah5, ah6, ah7, sb + OFF_X + aoff + 16u * 256u);
            uint32_t bh0, bh1, bh2, bh3, bh4, bh5, bh6, bh7;
            LDM4(bh0, bh1, bh2, bh3, sb + wb + boff);
            LDM4(bh4, bh5, bh6, bh7, sb + wb + boff + 16u * 256u);

            MMA16816(y[0][0], ah0, ah1, ah2, ah3, bh0, bh1);
            MMA16816(y[0][1], ah0, ah1, ah2, ah3, bh2, bh3);
            MMA16816(y[0][2], ah0, ah1, ah2, ah3, bh4, bh5);
            MMA16816(y[0][3], ah0, ah1, ah2, ah3, bh6, bh7);
            MMA16816(y[1][0], ah4, ah5, ah6, ah7, bh0, bh1);
            MMA16816(y[1][1], ah4, ah5, ah6, ah7, bh2, bh3);
            MMA16816(y[1][2], ah4, ah5, ah6, ah7, bh4, bh5);
            MMA16816(y[1][3], ah4, ah5, ah6, ah7, bh6, bh7);
        }

        // fold: acc += sim_row * (y + bias_col)
#pragma unroll
        for (int mt = 0; mt < 2; mt++) {
            const int rloc = mbw + mt * 16 + rql;
            const float s0 = s_sim[rloc * 9 + t];
            const float s1 = s_sim[(rloc + 8) * 9 + t];
#pragma unroll
            for (int nt = 0; nt < 4; nt++) {
                const int c = nbw + nt * 8 + cpl;
                const float bb0 = s_b[t * NTILE + c];
                const float bb1 = s_b[t * NTILE + c + 1];
                acc[mt][nt][0] = fmaf(s0, y[mt][nt][0] + bb0, acc[mt][nt][0]);
                acc[mt][nt][1] = fmaf(s0, y[mt][nt][1] + bb1, acc[mt][nt][1]);
                acc[mt][nt][2] = fmaf(s1, y[mt][nt][2] + bb0, acc[mt][nt][2]);
                acc[mt][nt][3] = fmaf(s1, y[mt][nt][3] + bb1, acc[mt][nt][3]);
            }
        }

        // pipeline: refill the buffer we just finished with W(t+2)
        if (t < T_DIM - 2) {
            __syncthreads();
            issue_w_tile(sb, OFF_W + (uint32_t)(t & 1) * 16384u, t + 2, nbase, tid);
            CP_COMMIT();
        }
        if (t < T_DIM - 1) {
            if (t < T_DIM - 2) { CP_WAIT1(); } else { CP_WAIT0(); }
            __syncthreads();
        }
    }

    // ---- Epilogue: residual (exact fp32 x from gmem) + store ----
#pragma unroll
    for (int mt = 0; mt < 2; mt++) {
        const int rg0 = row0 + mbw + mt * 16 + rql;
        const int rg1 = rg0 + 8;
#pragma unroll
        for (int nt = 0; nt < 4; nt++) {
            const int c = nbase + nbw + nt * 8 + cpl;
            float2 xv0 = *reinterpret_cast<const float2*>(x + (size_t)rg0 * D_DIM + c);
            float2 o0  = make_float2(acc[mt][nt][0] + xv0.x, acc[mt][nt][1] + xv0.y);
            *reinterpret_cast<float2*>(out + (size_t)rg0 * D_DIM + c) = o0;
            float2 xv1 = *reinterpret_cast<const float2*>(x + (size_t)rg1 * D_DIM + c);
            float2 o1  = make_float2(acc[mt][nt][2] + xv1.x, acc[mt][nt][3] + xv1.y);
            *reinterpret_cast<float2*>(out + (size_t)rg1 * D_DIM + c) = o1;
        }
    }
}

extern "C" void kernel_launch(void* const* d_in, const int* in_sizes, int n_in,
                              void* d_out, int out_size)
{
    (void)n_in; (void)out_size;
    const float* x = (const float*)d_in[0];   // [B,S,D]
    const float* W = (const float*)d_in[1];   // [T,D,D]
    const float* b = (const float*)d_in[2];   // [T,D]
    const float* p = (const float*)d_in[3];   // [T,1,D]
    float* out = (float*)d_out;

    const int nrows = in_sizes[0] / D_DIM;    // 65536
    const int grid  = (nrows / MTILE) * 2;    // 1024

    conv_kernel<<<128, 256>>>(W);

    cudaFuncSetAttribute(dt_mma_kernel,
                         cudaFuncAttributeMaxDynamicSharedMemorySize, SMEM_TOTAL);
    dt_mma_kernel<<<grid, THREADS, SMEM_TOTAL>>>(x, b, p, out);
}